// round 2
// baseline (speedup 1.0000x reference)
#include <cuda_runtime.h>
#include <cuda_bf16.h>

// AdaBoost fused classifier:
//   logits[N,E] = x[N,F] @ W[E,F]^T + b[E]
//   pred = (logit > 0)              (round-half-even of sigmoid: 0.5 -> 0)
//   acc[n] = sum_e (pred ? trunc(alpha[e]) : 0)
//   out[n] = sign(acc[n])
//
// fp32 CUDA-core register-tiled GEMM, BM=128 x BN=256(=E) x BK=16,
// 256 threads, per-thread 8x16 accumulator, fused epilogue with
// half-warp shuffle reduction over E. One kernel, no scratch.

#define BM 128
#define BN 256
#define BK 16
#define TM 8
#define TN 16

__global__ __launch_bounds__(256, 1)
void adaboost_kernel(const float* __restrict__ x,
                     const float* __restrict__ W,
                     const float* __restrict__ bvec,
                     const float* __restrict__ alphas,
                     float* __restrict__ out,
                     int F) {
    __shared__ float As[BK][BM];   // [k][m]
    __shared__ float Bs[BK][BN];   // [k][e]

    const int tid = threadIdx.x;
    const int ctx = tid & 15;      // 0..15 (column group)
    const int cty = tid >> 4;      // 0..15 (row group)
    const int m0  = blockIdx.x * BM;

    float acc[TM][TN];
#pragma unroll
    for (int i = 0; i < TM; i++)
#pragma unroll
        for (int j = 0; j < TN; j++) acc[i][j] = 0.0f;

    for (int k0 = 0; k0 < F; k0 += BK) {
        // ---- load A tile: 128 rows x 16 k = 512 float4, 2 per thread ----
#pragma unroll
        for (int l = 0; l < 2; l++) {
            int f   = tid + 256 * l;
            int row = f >> 2;             // 0..127
            int kc  = (f & 3) * 4;        // 0,4,8,12
            float4 v = *reinterpret_cast<const float4*>(
                x + (size_t)(m0 + row) * F + k0 + kc);
            As[kc + 0][row] = v.x;
            As[kc + 1][row] = v.y;
            As[kc + 2][row] = v.z;
            As[kc + 3][row] = v.w;
        }
        // ---- load B tile: 256 e x 16 k = 1024 float4, 4 per thread ----
#pragma unroll
        for (int l = 0; l < 4; l++) {
            int f  = tid + 256 * l;
            int e  = f >> 2;              // 0..255
            int kc = (f & 3) * 4;
            float4 v = *reinterpret_cast<const float4*>(
                W + (size_t)e * F + k0 + kc);
            Bs[kc + 0][e] = v.x;
            Bs[kc + 1][e] = v.y;
            Bs[kc + 2][e] = v.z;
            Bs[kc + 3][e] = v.w;
        }
        __syncthreads();

        // ---- compute: 16 k-steps, 8x16 FMA each ----
#pragma unroll
        for (int kk = 0; kk < BK; kk++) {
            float ra[TM], rb[TN];
            // rows owned: cty*4 + ig*64 + {0..3}
            float4 a0 = *reinterpret_cast<const float4*>(&As[kk][cty * 4]);
            float4 a1 = *reinterpret_cast<const float4*>(&As[kk][cty * 4 + 64]);
            ra[0] = a0.x; ra[1] = a0.y; ra[2] = a0.z; ra[3] = a0.w;
            ra[4] = a1.x; ra[5] = a1.y; ra[6] = a1.z; ra[7] = a1.w;
            // cols owned: ctx*4 + jg*64 + {0..3}
#pragma unroll
            for (int jg = 0; jg < 4; jg++) {
                float4 bq = *reinterpret_cast<const float4*>(
                    &Bs[kk][ctx * 4 + 64 * jg]);
                rb[jg * 4 + 0] = bq.x;
                rb[jg * 4 + 1] = bq.y;
                rb[jg * 4 + 2] = bq.z;
                rb[jg * 4 + 3] = bq.w;
            }
#pragma unroll
            for (int i = 0; i < TM; i++)
#pragma unroll
                for (int j = 0; j < TN; j++)
                    acc[i][j] = fmaf(ra[i], rb[j], acc[i][j]);
        }
        __syncthreads();
    }

    // ---- fused epilogue ----
    float bb[TN], ta[TN];
#pragma unroll
    for (int j = 0; j < TN; j++) {
        int c = ctx * 4 + (j >> 2) * 64 + (j & 3);
        bb[j] = __ldg(bvec + c);
        ta[j] = truncf(__ldg(alphas + c));
    }

    float part[TM];
#pragma unroll
    for (int i = 0; i < TM; i++) {
        float s = 0.0f;
#pragma unroll
        for (int j = 0; j < TN; j++) {
            float logit = acc[i][j] + bb[j];
            // pred = round(sigmoid(logit)): 1 iff logit > 0 (0.5 rounds to 0)
            if (logit > 0.0f) s += ta[j];
        }
        part[i] = s;
    }

    // reduce across the 16 threads sharing cty (contiguous half-warp)
#pragma unroll
    for (int i = 0; i < TM; i++) {
        part[i] += __shfl_xor_sync(0xffffffffu, part[i], 8);
        part[i] += __shfl_xor_sync(0xffffffffu, part[i], 4);
        part[i] += __shfl_xor_sync(0xffffffffu, part[i], 2);
        part[i] += __shfl_xor_sync(0xffffffffu, part[i], 1);
    }

    if (ctx == 0) {
#pragma unroll
        for (int i = 0; i < TM; i++) {
            int r = cty * 4 + (i >> 2) * 64 + (i & 3);
            float s = part[i];
            out[m0 + r] = (s > 0.0f) ? 1.0f : ((s < 0.0f) ? -1.0f : 0.0f);
        }
    }
}

extern "C" void kernel_launch(void* const* d_in, const int* in_sizes, int n_in,
                              void* d_out, int out_size) {
    const float* x      = (const float*)d_in[0];   // [N, F]
    const float* W      = (const float*)d_in[1];   // [E, F]
    const float* bvec   = (const float*)d_in[2];   // [E]
    const float* alphas = (const float*)d_in[3];   // [E]
    float* out = (float*)d_out;                    // [N]

    const int E = in_sizes[2];          // 256
    const int F = in_sizes[1] / E;      // 512
    const int N = in_sizes[0] / F;      // 131072

    dim3 grid(N / BM);
    dim3 block(256);
    adaboost_kernel<<<grid, block>>>(x, W, bvec, alphas, out, F);
}

// round 3
// speedup vs baseline: 1.0678x; 1.0678x over previous
#include <cuda_runtime.h>
#include <cuda_bf16.h>

// AdaBoost fused classifier:
//   logits[N,E] = x[N,F] @ W[E,F]^T + b[E]
//   pred = (logit > 0)          (round-half-even of sigmoid: 0.5 -> 0)
//   acc[n] = sum_e (pred ? trunc(alpha[e]) : 0)
//   out[n] = sign(acc[n])
//
// fp32 register-tiled GEMM using packed fma.rn.f32x2 (Blackwell FFMA2):
// 2 IEEE fp32 FMAs per issue slot -> 2x the scalar-FFMA rt=2 ceiling.
// BM=128 x BN=256(=E) x BK=16, 256 threads, per-thread 8 rows x 8 col-pairs.
// Global->register prefetch of the next K-tile overlaps with compute.

#define BM 128
#define BN 256
#define BK 16
#define TM 8
#define TNP 8   // column PAIRS per thread (16 columns)

__device__ __forceinline__ unsigned long long pack2(float a, float b) {
    unsigned long long r;
    asm("mov.b64 %0, {%1, %2};" : "=l"(r) : "f"(a), "f"(b));
    return r;
}
__device__ __forceinline__ void unpack2(unsigned long long v, float& lo, float& hi) {
    asm("mov.b64 {%0, %1}, %2;" : "=f"(lo), "=f"(hi) : "l"(v));
}

__global__ __launch_bounds__(256, 1)
void adaboost_kernel(const float* __restrict__ x,
                     const float* __restrict__ W,
                     const float* __restrict__ bvec,
                     const float* __restrict__ alphas,
                     float* __restrict__ out,
                     int F) {
    __shared__ float As[BK][BM];   // [k][m]
    __shared__ float Bs[BK][BN];   // [k][e]

    const int tid = threadIdx.x;
    const int ctx = tid & 15;      // 0..15 (column group)
    const int cty = tid >> 4;      // 0..15 (row group)
    const int m0  = blockIdx.x * BM;

    unsigned long long acc2[TM][TNP];
#pragma unroll
    for (int i = 0; i < TM; i++)
#pragma unroll
        for (int p = 0; p < TNP; p++) acc2[i][p] = 0ull;

    const int T = F / BK;

    // ---- prefetch tile 0 into registers ----
    float4 pa[2], pb[4];
#pragma unroll
    for (int l = 0; l < 2; l++) {
        int f   = tid + 256 * l;
        int row = f >> 2;
        int kc  = (f & 3) * 4;
        pa[l] = *reinterpret_cast<const float4*>(x + (size_t)(m0 + row) * F + kc);
    }
#pragma unroll
    for (int l = 0; l < 4; l++) {
        int f  = tid + 256 * l;
        int e  = f >> 2;
        int kc = (f & 3) * 4;
        pb[l] = *reinterpret_cast<const float4*>(W + (size_t)e * F + kc);
    }

    for (int t = 0; t < T; t++) {
        // ---- commit prefetched tile to smem ----
#pragma unroll
        for (int l = 0; l < 2; l++) {
            int f   = tid + 256 * l;
            int row = f >> 2;
            int kc  = (f & 3) * 4;
            As[kc + 0][row] = pa[l].x;
            As[kc + 1][row] = pa[l].y;
            As[kc + 2][row] = pa[l].z;
            As[kc + 3][row] = pa[l].w;
        }
#pragma unroll
        for (int l = 0; l < 4; l++) {
            int f  = tid + 256 * l;
            int e  = f >> 2;
            int kc = (f & 3) * 4;
            Bs[kc + 0][e] = pb[l].x;
            Bs[kc + 1][e] = pb[l].y;
            Bs[kc + 2][e] = pb[l].z;
            Bs[kc + 3][e] = pb[l].w;
        }
        __syncthreads();

        // ---- prefetch next tile (overlaps with compute below) ----
        if (t + 1 < T) {
            int k0n = (t + 1) * BK;
#pragma unroll
            for (int l = 0; l < 2; l++) {
                int f   = tid + 256 * l;
                int row = f >> 2;
                int kc  = (f & 3) * 4;
                pa[l] = *reinterpret_cast<const float4*>(
                    x + (size_t)(m0 + row) * F + k0n + kc);
            }
#pragma unroll
            for (int l = 0; l < 4; l++) {
                int f  = tid + 256 * l;
                int e  = f >> 2;
                int kc = (f & 3) * 4;
                pb[l] = *reinterpret_cast<const float4*>(
                    W + (size_t)e * F + k0n + kc);
            }
        }

        // ---- compute: 16 k-steps, 8x8 packed FMA2 each ----
#pragma unroll
        for (int kk = 0; kk < BK; kk++) {
            float4 a0 = *reinterpret_cast<const float4*>(&As[kk][cty * 4]);
            float4 a1 = *reinterpret_cast<const float4*>(&As[kk][cty * 4 + 64]);
            unsigned long long a2[TM];
            a2[0] = pack2(a0.x, a0.x);
            a2[1] = pack2(a0.y, a0.y);
            a2[2] = pack2(a0.z, a0.z);
            a2[3] = pack2(a0.w, a0.w);
            a2[4] = pack2(a1.x, a1.x);
            a2[5] = pack2(a1.y, a1.y);
            a2[6] = pack2(a1.z, a1.z);
            a2[7] = pack2(a1.w, a1.w);

            unsigned long long b2[TNP];
#pragma unroll
            for (int jg = 0; jg < 4; jg++) {
                ulonglong2 q = *reinterpret_cast<const ulonglong2*>(
                    &Bs[kk][ctx * 4 + 64 * jg]);
                b2[jg * 2 + 0] = q.x;   // cols base+0, base+1
                b2[jg * 2 + 1] = q.y;   // cols base+2, base+3
            }
#pragma unroll
            for (int i = 0; i < TM; i++)
#pragma unroll
                for (int p = 0; p < TNP; p++)
                    asm("fma.rn.f32x2 %0, %1, %2, %0;"
                        : "+l"(acc2[i][p])
                        : "l"(a2[i]), "l"(b2[p]));
        }
        __syncthreads();
    }

    // ---- fused epilogue ----
    float bb[2 * TNP], ta[2 * TNP];
#pragma unroll
    for (int p = 0; p < TNP; p++) {
        int cbase = ctx * 4 + 64 * (p >> 1) + (p & 1) * 2;
        bb[2 * p + 0] = __ldg(bvec + cbase);
        bb[2 * p + 1] = __ldg(bvec + cbase + 1);
        ta[2 * p + 0] = truncf(__ldg(alphas + cbase));
        ta[2 * p + 1] = truncf(__ldg(alphas + cbase + 1));
    }

    float part[TM];
#pragma unroll
    for (int i = 0; i < TM; i++) {
        float s = 0.0f;
#pragma unroll
        for (int p = 0; p < TNP; p++) {
            float lo, hi;
            unpack2(acc2[i][p], lo, hi);
            if (lo + bb[2 * p + 0] > 0.0f) s += ta[2 * p + 0];
            if (hi + bb[2 * p + 1] > 0.0f) s += ta[2 * p + 1];
        }
        part[i] = s;
    }

    // reduce across the 16 threads sharing cty (contiguous half-warp)
#pragma unroll
    for (int i = 0; i < TM; i++) {
        part[i] += __shfl_xor_sync(0xffffffffu, part[i], 8);
        part[i] += __shfl_xor_sync(0xffffffffu, part[i], 4);
        part[i] += __shfl_xor_sync(0xffffffffu, part[i], 2);
        part[i] += __shfl_xor_sync(0xffffffffu, part[i], 1);
    }

    if (ctx == 0) {
#pragma unroll
        for (int i = 0; i < TM; i++) {
            int r = cty * 4 + (i >> 2) * 64 + (i & 3);
            float s = part[i];
            out[m0 + r] = (s > 0.0f) ? 1.0f : ((s < 0.0f) ? -1.0f : 0.0f);
        }
    }
}

extern "C" void kernel_launch(void* const* d_in, const int* in_sizes, int n_in,
                              void* d_out, int out_size) {
    const float* x      = (const float*)d_in[0];   // [N, F]
    const float* W      = (const float*)d_in[1];   // [E, F]
    const float* bvec   = (const float*)d_in[2];   // [E]
    const float* alphas = (const float*)d_in[3];   // [E]
    float* out = (float*)d_out;                    // [N]

    const int E = in_sizes[2];          // 256
    const int F = in_sizes[1] / E;      // 512
    const int N = in_sizes[0] / F;      // 131072

    dim3 grid(N / BM);
    dim3 block(256);
    adaboost_kernel<<<grid, block>>>(x, W, bvec, alphas, out, F);
}